// round 3
// baseline (speedup 1.0000x reference)
#include <cuda_runtime.h>
#include <math.h>

#define B   32
#define NF  128
#define DE  256
#define DH  512
#define G   2
#define SL  8

// ---- device scratch (no allocations allowed) ----
__device__ float g_query[B * DE];
__device__ float g_attin[B * NF * G];
__device__ float g_bufA[B * NF * NF];
__device__ float g_bufB[B * NF * NF];
__device__ float g_final[B * NF * NF];
__device__ float g_finalT[B * NF * NF];
__device__ float g_attout[B * NF * G];

__device__ __forceinline__ void cp_async16(void* smem_dst, const void* gmem_src) {
    unsigned sa = (unsigned)__cvta_generic_to_shared(smem_dst);
    asm volatile("cp.async.ca.shared.global [%0], [%1], 16;" :: "r"(sa), "l"(gmem_src));
}

// ============================================================================
// Kernel 1: query = c_i @ W^T + b, and att_in = einsum('bngs,bs->bng')
// grid(B), block(256)
// ============================================================================
__global__ __launch_bounds__(256) void query_kernel(
    const float* __restrict__ c_i, const float* __restrict__ W,
    const float* __restrict__ bias,
    const float* __restrict__ att_stack, const float* __restrict__ stack_ptr)
{
    int b = blockIdx.x;
    int t = threadIdx.x;
    __shared__ float csh[DH];
    csh[t]       = c_i[b * DH + t];
    csh[t + 256] = c_i[b * DH + t + 256];
    __syncthreads();

    int w = t >> 5, lane = t & 31;
    for (int d = w; d < DE; d += 8) {
        const float* Wr = W + (size_t)d * DH;
        float s = 0.f;
        #pragma unroll
        for (int i = 0; i < DH / 32; i++)
            s += Wr[lane + 32 * i] * csh[lane + 32 * i];
        #pragma unroll
        for (int o = 16; o; o >>= 1) s += __shfl_xor_sync(~0u, s, o);
        if (lane == 0) g_query[b * DE + d] = s + bias[d];
    }

    {
        int n = t >> 1, g = t & 1;
        const float* as = att_stack + (((size_t)b * NF + n) * G + g) * SL;
        const float* sp = stack_ptr + b * SL;
        float s = 0.f;
        #pragma unroll
        for (int ss = 0; ss < SL; ss++) s += as[ss] * sp[ss];
        g_attin[(b * NF + n) * G + g] = s;
    }
}

// ============================================================================
// Kernel 2: mask power step, cp.async double-buffered, 256 threads.
// next = (cur @ M) * 0.9 ; final (+)= next.  Step 2 also writes final^T.
// grid(8, B), block(256). 16 output rows/block, 2x4 register tile/thread.
// ============================================================================
__global__ __launch_bounds__(256) void maskpow_kernel(
    const float* __restrict__ relmask, int step)
{
    int b  = blockIdx.y;
    int n0 = blockIdx.x * 16;
    const float* Mb = relmask + (size_t)b * NF * NF;
    const float* cb = (step == 0 ? relmask : (step == 1 ? (const float*)g_bufA
                                                        : (const float*)g_bufB))
                      + (size_t)b * NF * NF;
    float* outb = (step == 1 ? g_bufB : g_bufA) + (size_t)b * NF * NF;
    float* fin  = g_final + (size_t)b * NF * NF;

    __shared__ float csh[16][NF];       // also reused as the final tile for transpose
    __shared__ float msh[2][32][NF];
    int t = threadIdx.x;

    // prefetch c tile (16x128): 512 float4, 2 per thread
    {
        const float4* src = (const float4*)(cb + (size_t)n0 * NF);
        float4* dst = (float4*)&csh[0][0];
        cp_async16(dst + t,       src + t);
        cp_async16(dst + t + 256, src + t + 256);
    }
    // prefetch M k-tile 0 (32x128): 1024 float4, 4 per thread
    {
        const float4* src = (const float4*)Mb;
        float4* dst = (float4*)&msh[0][0][0];
        #pragma unroll
        for (int i = 0; i < 4; i++)
            cp_async16(dst + t + 256 * i, src + t + 256 * i);
    }
    asm volatile("cp.async.commit_group;");

    float acc[2][4] = {};
    int tn = (t >> 5) * 2;       // warp w -> rows 2w, 2w+1
    int tm = (t & 31) * 4;

    for (int kt = 0; kt < 4; kt++) {
        if (kt < 3) {
            const float4* src = (const float4*)(Mb + (size_t)(kt + 1) * 32 * NF);
            float4* dst = (float4*)&msh[(kt + 1) & 1][0][0];
            #pragma unroll
            for (int i = 0; i < 4; i++)
                cp_async16(dst + t + 256 * i, src + t + 256 * i);
            asm volatile("cp.async.commit_group;");
            asm volatile("cp.async.wait_group 1;");
        } else {
            asm volatile("cp.async.wait_group 0;");
        }
        __syncthreads();

        const float (*mb)[NF] = msh[kt & 1];
        #pragma unroll
        for (int kk4 = 0; kk4 < 8; kk4++) {
            float cva[4], cvb[4];
            *(float4*)cva = *(const float4*)&csh[tn + 0][kt * 32 + kk4 * 4];
            *(float4*)cvb = *(const float4*)&csh[tn + 1][kt * 32 + kk4 * 4];
            #pragma unroll
            for (int j = 0; j < 4; j++) {
                float4 mv = *(const float4*)&mb[kk4 * 4 + j][tm];
                acc[0][0] += cva[j] * mv.x; acc[0][1] += cva[j] * mv.y;
                acc[0][2] += cva[j] * mv.z; acc[0][3] += cva[j] * mv.w;
                acc[1][0] += cvb[j] * mv.x; acc[1][1] += cvb[j] * mv.y;
                acc[1][2] += cvb[j] * mv.z; acc[1][3] += cvb[j] * mv.w;
            }
        }
        __syncthreads();
    }

    float4 fsave[2];
    #pragma unroll
    for (int i = 0; i < 2; i++) {
        int n = n0 + tn + i;
        size_t base = (size_t)n * NF + tm;
        float4 v;
        v.x = 0.9f * acc[i][0]; v.y = 0.9f * acc[i][1];
        v.z = 0.9f * acc[i][2]; v.w = 0.9f * acc[i][3];
        *(float4*)&outb[base] = v;
        float4 f;
        if (step == 0) {
            float4 mm = *(const float4*)&Mb[base];
            f.x = mm.x + v.x; f.y = mm.y + v.y; f.z = mm.z + v.z; f.w = mm.w + v.w;
        } else {
            float4 pf = *(const float4*)&fin[base];
            f.x = pf.x + v.x; f.y = pf.y + v.y; f.z = pf.z + v.z; f.w = pf.w + v.w;
        }
        *(float4*)&fin[base] = f;
        fsave[i] = f;
    }

    if (step == 2) {
        // stage the 16x128 final tile in smem (reuse csh), write transposed
        #pragma unroll
        for (int i = 0; i < 2; i++)
            *(float4*)&csh[tn + i][tm] = fsave[i];
        __syncthreads();
        int m = t >> 1, half = (t & 1) * 8;
        float v[8];
        #pragma unroll
        for (int i = 0; i < 8; i++) v[i] = csh[half + i][m];
        float* dstT = g_finalT + ((size_t)b * NF + m) * NF + n0 + half;
        *(float4*)&dstT[0] = make_float4(v[0], v[1], v[2], v[3]);
        *(float4*)&dstT[4] = make_float4(v[4], v[5], v[6], v[7]);
    }
}

// ============================================================================
// Kernel 3: main stream.  Block = (b, m).  Two interleaved n-chains per warp.
//   weit = sigmoid(feat_edge[b,n,m,:] . query[b,:]) * final_mask[b,n,m]
//   att_out[b,m,g] += att_in[b,n,g] * weit        (block-local, no atomics)
// grid(B*NF), block(256) = 8 warps, each warp handles 16 n (2 at a time).
// ============================================================================
__global__ __launch_bounds__(256) void main_kernel(const float* __restrict__ fe)
{
    int bid = blockIdx.x;
    int b = bid >> 7;
    int m = bid & 127;
    __shared__ float qsh[DE];
    __shared__ float ash[NF * G];
    __shared__ float msk[NF];
    __shared__ float part[8][2];

    int t = threadIdx.x;
    qsh[t] = g_query[b * DE + t];
    ash[t] = g_attin[b * NF * G + t];
    if (t < NF) msk[t] = g_finalT[((size_t)b * NF + m) * NF + t];   // coalesced
    __syncthreads();

    int w = t >> 5, lane = t & 31;
    float4 q1 = *(const float4*)&qsh[lane * 4];
    float4 q2 = *(const float4*)&qsh[128 + lane * 4];
    const float* febase = fe + (((size_t)b * NF) * NF + m) * DE;

    float p0 = 0.f, p1 = 0.f;
    #pragma unroll
    for (int j = 0; j < 8; j++) {
        int n1 = w + 16 * j;
        int n2 = n1 + 8;
        const float4* rowA = (const float4*)(febase + (size_t)n1 * NF * DE);
        const float4* rowB = (const float4*)(febase + (size_t)n2 * NF * DE);
        float4 a1 = rowA[lane];
        float4 a2 = rowA[lane + 32];
        float4 b1 = rowB[lane];
        float4 b2 = rowB[lane + 32];
        float s1 = a1.x * q1.x + a1.y * q1.y + a1.z * q1.z + a1.w * q1.w
                 + a2.x * q2.x + a2.y * q2.y + a2.z * q2.z + a2.w * q2.w;
        float s2 = b1.x * q1.x + b1.y * q1.y + b1.z * q1.z + b1.w * q1.w
                 + b2.x * q2.x + b2.y * q2.y + b2.z * q2.z + b2.w * q2.w;
        #pragma unroll
        for (int o = 16; o; o >>= 1) {
            s1 += __shfl_xor_sync(~0u, s1, o);
            s2 += __shfl_xor_sync(~0u, s2, o);
        }
        float w1 = msk[n1] / (1.f + __expf(-s1));
        float w2 = msk[n2] / (1.f + __expf(-s2));
        p0 += ash[n1 * 2]     * w1 + ash[n2 * 2]     * w2;
        p1 += ash[n1 * 2 + 1] * w1 + ash[n2 * 2 + 1] * w2;
    }
    if (lane == 0) { part[w][0] = p0; part[w][1] = p1; }
    __syncthreads();
    if (t < 2) {
        float s = 0.f;
        #pragma unroll
        for (int i = 0; i < 8; i++) s += part[i][t];
        g_attout[((size_t)b * NF + m) * G + t] = s;
    }
}

// ============================================================================
// Kernel 4: normalize + blend + write all four outputs.
// grid(B), block(256)
// ============================================================================
__global__ __launch_bounds__(256) void finalize_kernel(
    const float* __restrict__ att_stack, const float* __restrict__ stack_ptr,
    float* __restrict__ out)
{
    int b = blockIdx.x;
    int t = threadIdx.x;
    __shared__ float att[NF * G];
    __shared__ float norm[G];
    __shared__ float sps[SL];

    att[t] = g_attout[b * NF * G + t];
    if (t < SL) sps[t] = stack_ptr[b * SL + t];
    __syncthreads();

    if (t < 64) {
        int g = t >> 5, lane = t & 31;
        float mx = -1e30f;
        for (int i = lane; i < NF; i += 32) mx = fmaxf(mx, att[i * G + g]);
        #pragma unroll
        for (int o = 16; o; o >>= 1) mx = fmaxf(mx, __shfl_xor_sync(~0u, mx, o));
        if (lane == 0) norm[g] = (mx <= 1.f) ? 1.f : mx;
    }
    __syncthreads();

    const float* asb = att_stack + (size_t)b * NF * G * SL;
    float* ob = out + (size_t)b * NF * G * SL;
    for (int idx = t; idx < NF * G * SL; idx += 256) {
        int s = idx & 7;
        int g = (idx >> 3) & 1;
        int n = idx >> 4;
        float a  = att[n * G + g] / norm[g];
        float sp = sps[s];
        ob[idx] = a * sp + asb[idx] * (1.f - sp);
    }
    if (t < SL) out[(size_t)B * NF * G * SL + b * SL + t] = sps[t];
    float* z = out + (size_t)B * NF * G * SL + (size_t)B * SL;
    for (int i = t; i < DH; i += 256) {
        z[(size_t)b * DH + i] = 0.f;
        z[(size_t)B * DH + (size_t)b * DH + i] = 0.f;
    }
}

// ============================================================================
extern "C" void kernel_launch(void* const* d_in, const int* in_sizes, int n_in,
                              void* d_out, int out_size)
{
    const float* feat_edge = (const float*)d_in[2];
    const float* c_i       = (const float*)d_in[3];
    const float* relmask   = (const float*)d_in[4];
    const float* att_stack = (const float*)d_in[5];
    const float* stack_ptr = (const float*)d_in[6];
    const float* map_c_w   = (const float*)d_in[8];
    const float* map_c_b   = (const float*)d_in[9];
    float* out = (float*)d_out;

    query_kernel<<<B, 256>>>(c_i, map_c_w, map_c_b, att_stack, stack_ptr);
    maskpow_kernel<<<dim3(8, B), 256>>>(relmask, 0);
    maskpow_kernel<<<dim3(8, B), 256>>>(relmask, 1);
    maskpow_kernel<<<dim3(8, B), 256>>>(relmask, 2);
    main_kernel<<<B * NF, 256>>>(feat_edge);
    finalize_kernel<<<B, 256>>>(att_stack, stack_ptr, out);
}

// round 4
// speedup vs baseline: 1.1899x; 1.1899x over previous
#include <cuda_runtime.h>
#include <math.h>

#define B   32
#define NF  128
#define DE  256
#define DH  512
#define G   2
#define SL  8

// ---- device scratch (no allocations allowed) ----
__device__ float g_query[B * DE];
__device__ float g_attin[B * NF * G];
__device__ float g_finalT[B * NF * NF];
__device__ float g_attout[B * NF * G];

__device__ __forceinline__ void cp_async16(void* smem_dst, const void* gmem_src) {
    unsigned sa = (unsigned)__cvta_generic_to_shared(smem_dst);
    asm volatile("cp.async.ca.shared.global [%0], [%1], 16;" :: "r"(sa), "l"(gmem_src));
}

// ============================================================================
// Kernel 1 (fused prep): grid = 256 mask blocks + 32 query blocks, 256 thr.
//
// Mask blocks (bid < 256): fused 3-step mask power chain, block-local.
//   csh (16 rows of cur) stays in smem across steps; M streamed per step via
//   cp.async double buffer; final accumulated in regs; only final^T written.
// Query blocks (bid >= 256): query = c_i @ W^T + b ; att_in einsum.
// ============================================================================
__global__ __launch_bounds__(256) void prep_kernel(
    const float* __restrict__ relmask,
    const float* __restrict__ c_i, const float* __restrict__ W,
    const float* __restrict__ bias,
    const float* __restrict__ att_stack, const float* __restrict__ stack_ptr)
{
    int bid = blockIdx.x;
    int t = threadIdx.x;

    if (bid >= 256) {
        // ---------------- query + att_in ----------------
        int b = bid - 256;
        __shared__ float qc[DH];
        qc[t]       = c_i[b * DH + t];
        qc[t + 256] = c_i[b * DH + t + 256];
        __syncthreads();

        int w = t >> 5, lane = t & 31;
        for (int d = w; d < DE; d += 8) {
            const float* Wr = W + (size_t)d * DH;
            float s = 0.f;
            #pragma unroll
            for (int i = 0; i < DH / 32; i++)
                s += Wr[lane + 32 * i] * qc[lane + 32 * i];
            #pragma unroll
            for (int o = 16; o; o >>= 1) s += __shfl_xor_sync(~0u, s, o);
            if (lane == 0) g_query[b * DE + d] = s + bias[d];
        }
        {
            int n = t >> 1, g = t & 1;
            const float* as = att_stack + (((size_t)b * NF + n) * G + g) * SL;
            const float* sp = stack_ptr + b * SL;
            float s = 0.f;
            #pragma unroll
            for (int ss = 0; ss < SL; ss++) s += as[ss] * sp[ss];
            g_attin[(b * NF + n) * G + g] = s;
        }
        return;
    }

    // ---------------- fused mask powers ----------------
    int b  = bid >> 3;
    int n0 = (bid & 7) * 16;
    const float* Mb = relmask + (size_t)b * NF * NF;

    __shared__ float csh[16][NF];        // cur tile, persists across steps
    __shared__ float msh[2][32][NF];     // double-buffered M k-tile

    // prefetch cur tile = relmask rows n0..n0+15 (8KB) and M k-tile 0
    {
        const float4* src = (const float4*)(Mb + (size_t)n0 * NF);
        float4* dst = (float4*)&csh[0][0];
        cp_async16(dst + t,       src + t);
        cp_async16(dst + t + 256, src + t + 256);
    }
    {
        const float4* src = (const float4*)Mb;
        float4* dst = (float4*)&msh[0][0][0];
        #pragma unroll
        for (int i = 0; i < 4; i++)
            cp_async16(dst + t + 256 * i, src + t + 256 * i);
    }
    asm volatile("cp.async.commit_group;");
    asm volatile("cp.async.wait_group 0;");
    __syncthreads();

    int tn = (t >> 5) * 2;   // warp-uniform: rows 2w, 2w+1
    int tm = (t & 31) * 4;

    // final accumulator starts at M tile (the "+ relation_mask" term)
    float f0[4], f1[4];
    *(float4*)f0 = *(const float4*)&csh[tn + 0][tm];
    *(float4*)f1 = *(const float4*)&csh[tn + 1][tm];

    for (int step = 0; step < 3; step++) {
        float acc0[4] = {}, acc1[4] = {};
        if (step > 0) {
            // prefetch M k-tile 0 for this step
            const float4* src = (const float4*)Mb;
            float4* dst = (float4*)&msh[0][0][0];
            #pragma unroll
            for (int i = 0; i < 4; i++)
                cp_async16(dst + t + 256 * i, src + t + 256 * i);
            asm volatile("cp.async.commit_group;");
        }
        for (int kt = 0; kt < 4; kt++) {
            if (kt < 3) {
                const float4* src = (const float4*)(Mb + (size_t)(kt + 1) * 32 * NF);
                float4* dst = (float4*)&msh[(kt + 1) & 1][0][0];
                #pragma unroll
                for (int i = 0; i < 4; i++)
                    cp_async16(dst + t + 256 * i, src + t + 256 * i);
                asm volatile("cp.async.commit_group;");
                asm volatile("cp.async.wait_group 1;");
            } else {
                asm volatile("cp.async.wait_group 0;");
            }
            __syncthreads();

            const float (*mb)[NF] = msh[kt & 1];
            #pragma unroll
            for (int kk4 = 0; kk4 < 8; kk4++) {
                float cva[4], cvb[4];
                *(float4*)cva = *(const float4*)&csh[tn + 0][kt * 32 + kk4 * 4];
                *(float4*)cvb = *(const float4*)&csh[tn + 1][kt * 32 + kk4 * 4];
                #pragma unroll
                for (int j = 0; j < 4; j++) {
                    float ca = cva[j], cb2 = cvb[j];
                    if (ca != 0.f || cb2 != 0.f) {   // warp-uniform skip
                        float4 mv = *(const float4*)&mb[kk4 * 4 + j][tm];
                        acc0[0] += ca * mv.x;  acc0[1] += ca * mv.y;
                        acc0[2] += ca * mv.z;  acc0[3] += ca * mv.w;
                        acc1[0] += cb2 * mv.x; acc1[1] += cb2 * mv.y;
                        acc1[2] += cb2 * mv.z; acc1[3] += cb2 * mv.w;
                    }
                }
            }
            __syncthreads();
        }
        // cur = 0.9 * acc ; final += cur ; write cur back to csh (warp-private rows)
        float4 c0, c1;
        c0.x = 0.9f * acc0[0]; c0.y = 0.9f * acc0[1];
        c0.z = 0.9f * acc0[2]; c0.w = 0.9f * acc0[3];
        c1.x = 0.9f * acc1[0]; c1.y = 0.9f * acc1[1];
        c1.z = 0.9f * acc1[2]; c1.w = 0.9f * acc1[3];
        f0[0] += c0.x; f0[1] += c0.y; f0[2] += c0.z; f0[3] += c0.w;
        f1[0] += c1.x; f1[1] += c1.y; f1[2] += c1.z; f1[3] += c1.w;
        __syncwarp();
        *(float4*)&csh[tn + 0][tm] = c0;
        *(float4*)&csh[tn + 1][tm] = c1;
        __syncwarp();
    }

    // stage final tile into csh, then write transposed to g_finalT
    __syncthreads();
    *(float4*)&csh[tn + 0][tm] = *(float4*)f0;
    *(float4*)&csh[tn + 1][tm] = *(float4*)f1;
    __syncthreads();
    {
        int m = t >> 1, half = (t & 1) * 8;
        float v[8];
        #pragma unroll
        for (int i = 0; i < 8; i++) v[i] = csh[half + i][m];
        float* dstT = g_finalT + ((size_t)b * NF + m) * NF + n0 + half;
        *(float4*)&dstT[0] = make_float4(v[0], v[1], v[2], v[3]);
        *(float4*)&dstT[4] = make_float4(v[4], v[5], v[6], v[7]);
    }
}

// ============================================================================
// Kernel 2: main stream.  Block = (b, m).  Quarter-warp dot products:
// each warp handles 4 rows (n) per iteration via 8-lane sub-groups.
// grid(B*NF), block(256) = 8 warps x 16 rows each.
// ============================================================================
__global__ __launch_bounds__(256) void main_kernel(const float* __restrict__ fe)
{
    int bid = blockIdx.x;
    int b = bid >> 7;
    int m = bid & 127;
    __shared__ float qsh[DE];
    __shared__ float ash[NF * G];
    __shared__ float msk[NF];
    __shared__ float part[8][2];

    int t = threadIdx.x;
    qsh[t] = g_query[b * DE + t];
    ash[t] = g_attin[b * NF * G + t];
    if (t < NF) msk[t] = g_finalT[((size_t)b * NF + m) * NF + t];   // coalesced
    __syncthreads();

    int w = t >> 5, lane = t & 31;
    int qq = lane >> 3, sub = lane & 7;

    // each lane's slice of query: float4 index sub + 8c  (c = 0..7)
    float4 qv[8];
    #pragma unroll
    for (int c = 0; c < 8; c++) qv[c] = ((const float4*)qsh)[sub + 8 * c];

    float p0 = 0.f, p1 = 0.f;
    #pragma unroll
    for (int j = 0; j < 4; j++) {
        int n = w + 8 * (4 * j + qq);
        const float4* row = (const float4*)(fe + (((size_t)b * NF + n) * NF + m) * DE);
        float4 fv[8];
        #pragma unroll
        for (int c = 0; c < 8; c++) fv[c] = row[sub + 8 * c];

        float sA = 0.f, sB = 0.f;
        #pragma unroll
        for (int c = 0; c < 8; c += 2) {
            sA += fv[c].x * qv[c].x + fv[c].y * qv[c].y
                + fv[c].z * qv[c].z + fv[c].w * qv[c].w;
            sB += fv[c+1].x * qv[c+1].x + fv[c+1].y * qv[c+1].y
                + fv[c+1].z * qv[c+1].z + fv[c+1].w * qv[c+1].w;
        }
        float s = sA + sB;
        s += __shfl_xor_sync(~0u, s, 1);
        s += __shfl_xor_sync(~0u, s, 2);
        s += __shfl_xor_sync(~0u, s, 4);
        float wv = msk[n] / (1.f + __expf(-s));
        p0 += ash[n * 2]     * wv;
        p1 += ash[n * 2 + 1] * wv;
    }
    // sum the 4 quarter-groups (each group's lanes hold identical partials)
    p0 += __shfl_xor_sync(~0u, p0, 8);
    p0 += __shfl_xor_sync(~0u, p0, 16);
    p1 += __shfl_xor_sync(~0u, p1, 8);
    p1 += __shfl_xor_sync(~0u, p1, 16);

    if (lane == 0) { part[w][0] = p0; part[w][1] = p1; }
    __syncthreads();
    if (t < 2) {
        float s = 0.f;
        #pragma unroll
        for (int i = 0; i < 8; i++) s += part[i][t];
        g_attout[((size_t)b * NF + m) * G + t] = s;
    }
}

// ============================================================================
// Kernel 3: normalize + blend + write all four outputs.  grid(B), block(256)
// ============================================================================
__global__ __launch_bounds__(256) void finalize_kernel(
    const float* __restrict__ att_stack, const float* __restrict__ stack_ptr,
    float* __restrict__ out)
{
    int b = blockIdx.x;
    int t = threadIdx.x;
    __shared__ float att[NF * G];
    __shared__ float norm[G];
    __shared__ float sps[SL];

    att[t] = g_attout[b * NF * G + t];
    if (t < SL) sps[t] = stack_ptr[b * SL + t];
    __syncthreads();

    if (t < 64) {
        int g = t >> 5, lane = t & 31;
        float mx = -1e30f;
        for (int i = lane; i < NF; i += 32) mx = fmaxf(mx, att[i * G + g]);
        #pragma unroll
        for (int o = 16; o; o >>= 1) mx = fmaxf(mx, __shfl_xor_sync(~0u, mx, o));
        if (lane == 0) norm[g] = (mx <= 1.f) ? 1.f : mx;
    }
    __syncthreads();

    const float* asb = att_stack + (size_t)b * NF * G * SL;
    float* ob = out + (size_t)b * NF * G * SL;
    for (int idx = t; idx < NF * G * SL; idx += 256) {
        int s = idx & 7;
        int g = (idx >> 3) & 1;
        int n = idx >> 4;
        float a  = att[n * G + g] / norm[g];
        float sp = sps[s];
        ob[idx] = a * sp + asb[idx] * (1.f - sp);
    }
    if (t < SL) out[(size_t)B * NF * G * SL + b * SL + t] = sps[t];
    float* z = out + (size_t)B * NF * G * SL + (size_t)B * SL;
    for (int i = t; i < DH; i += 256) {
        z[(size_t)b * DH + i] = 0.f;
        z[(size_t)B * DH + (size_t)b * DH + i] = 0.f;
    }
}

// ============================================================================
extern "C" void kernel_launch(void* const* d_in, const int* in_sizes, int n_in,
                              void* d_out, int out_size)
{
    const float* feat_edge = (const float*)d_in[2];
    const float* c_i       = (const float*)d_in[3];
    const float* relmask   = (const float*)d_in[4];
    const float* att_stack = (const float*)d_in[5];
    const float* stack_ptr = (const float*)d_in[6];
    const float* map_c_w   = (const float*)d_in[8];
    const float* map_c_b   = (const float*)d_in[9];
    float* out = (float*)d_out;

    prep_kernel<<<256 + B, 256>>>(relmask, c_i, map_c_w, map_c_b,
                                  att_stack, stack_ptr);
    main_kernel<<<B * NF, 256>>>(feat_edge);
    finalize_kernel<<<B, 256>>>(att_stack, stack_ptr, out);
}

// round 5
// speedup vs baseline: 1.2477x; 1.0486x over previous
#include <cuda_runtime.h>
#include <math.h>

#define B   32
#define NF  128
#define DE  256
#define DH  512
#define G   2
#define SL  8

// ---- device scratch (no allocations allowed) ----
__device__ float g_query[B * DE];
__device__ float g_attin[B * NF * G];
__device__ float g_P[B * NF * NF];      // M @ M
__device__ float g_R[B * NF * NF];      // 0.81*M + 0.729*P
__device__ float g_finalT[B * NF * NF];
__device__ float g_attout[B * NF * G];

__device__ __forceinline__ void cp_async16(void* smem_dst, const void* gmem_src) {
    unsigned sa = (unsigned)__cvta_generic_to_shared(smem_dst);
    asm volatile("cp.async.ca.shared.global [%0], [%1], 16;" :: "r"(sa), "l"(gmem_src));
}

// ============================================================================
// Kernel A: P = M@M (sparse x sparse, ~90% FMA skipped), R = 0.81M + 0.729P.
// Query blocks (bid >= 256) ride along: query = c_i@W^T + b ; att_in einsum.
// grid(256 + 32), block(256).
// ============================================================================
__global__ __launch_bounds__(256) void prepA_kernel(
    const float* __restrict__ relmask,
    const float* __restrict__ c_i, const float* __restrict__ W,
    const float* __restrict__ bias,
    const float* __restrict__ att_stack, const float* __restrict__ stack_ptr)
{
    int bid = blockIdx.x;
    int t = threadIdx.x;

    if (bid >= 256) {
        int b = bid - 256;
        __shared__ float qc[DH];
        qc[t]       = c_i[b * DH + t];
        qc[t + 256] = c_i[b * DH + t + 256];
        __syncthreads();

        int w = t >> 5, lane = t & 31;
        for (int d = w; d < DE; d += 8) {
            const float* Wr = W + (size_t)d * DH;
            float s = 0.f;
            #pragma unroll
            for (int i = 0; i < DH / 32; i++)
                s += Wr[lane + 32 * i] * qc[lane + 32 * i];
            #pragma unroll
            for (int o = 16; o; o >>= 1) s += __shfl_xor_sync(~0u, s, o);
            if (lane == 0) g_query[b * DE + d] = s + bias[d];
        }
        {
            int n = t >> 1, g = t & 1;
            const float* as = att_stack + (((size_t)b * NF + n) * G + g) * SL;
            const float* sp = stack_ptr + b * SL;
            float s = 0.f;
            #pragma unroll
            for (int ss = 0; ss < SL; ss++) s += as[ss] * sp[ss];
            g_attin[(b * NF + n) * G + g] = s;
        }
        return;
    }

    int b  = bid >> 3;
    int n0 = (bid & 7) * 16;
    const float* Mb = relmask + (size_t)b * NF * NF;

    __shared__ float csh[16][NF];        // M rows n0..n0+15 (left operand)
    __shared__ float msh[2][32][NF];     // double-buffered M k-tile

    {
        const float4* src = (const float4*)(Mb + (size_t)n0 * NF);
        float4* dst = (float4*)&csh[0][0];
        cp_async16(dst + t,       src + t);
        cp_async16(dst + t + 256, src + t + 256);
    }
    {
        const float4* src = (const float4*)Mb;
        float4* dst = (float4*)&msh[0][0][0];
        #pragma unroll
        for (int i = 0; i < 4; i++)
            cp_async16(dst + t + 256 * i, src + t + 256 * i);
    }
    asm volatile("cp.async.commit_group;");
    asm volatile("cp.async.wait_group 0;");
    __syncthreads();

    int tn = (t >> 5) * 2;
    int tm = (t & 31) * 4;

    float acc0[4] = {}, acc1[4] = {};
    for (int kt = 0; kt < 4; kt++) {
        if (kt < 3) {
            const float4* src = (const float4*)(Mb + (size_t)(kt + 1) * 32 * NF);
            float4* dst = (float4*)&msh[(kt + 1) & 1][0][0];
            #pragma unroll
            for (int i = 0; i < 4; i++)
                cp_async16(dst + t + 256 * i, src + t + 256 * i);
            asm volatile("cp.async.commit_group;");
            asm volatile("cp.async.wait_group 1;");
        } else {
            asm volatile("cp.async.wait_group 0;");
        }
        __syncthreads();

        const float (*mb)[NF] = msh[kt & 1];
        #pragma unroll
        for (int kk4 = 0; kk4 < 8; kk4++) {
            float cva[4], cvb[4];
            *(float4*)cva = *(const float4*)&csh[tn + 0][kt * 32 + kk4 * 4];
            *(float4*)cvb = *(const float4*)&csh[tn + 1][kt * 32 + kk4 * 4];
            #pragma unroll
            for (int j = 0; j < 4; j++) {
                float ca = cva[j], cb2 = cvb[j];
                if (ca != 0.f || cb2 != 0.f) {   // warp-uniform skip (~90%)
                    float4 mv = *(const float4*)&mb[kk4 * 4 + j][tm];
                    acc0[0] += ca * mv.x;  acc0[1] += ca * mv.y;
                    acc0[2] += ca * mv.z;  acc0[3] += ca * mv.w;
                    acc1[0] += cb2 * mv.x; acc1[1] += cb2 * mv.y;
                    acc1[2] += cb2 * mv.z; acc1[3] += cb2 * mv.w;
                }
            }
        }
        __syncthreads();
    }

    // write P and R = 0.81*M + 0.729*P
    #pragma unroll
    for (int i = 0; i < 2; i++) {
        const float* acc = (i == 0) ? acc0 : acc1;
        size_t base = ((size_t)b * NF + n0 + tn + i) * NF + tm;
        float4 p = make_float4(acc[0], acc[1], acc[2], acc[3]);
        *(float4*)&g_P[base] = p;
        float4 mm = *(const float4*)&csh[tn + i][tm];
        float4 r;
        r.x = 0.81f * mm.x + 0.729f * p.x;
        r.y = 0.81f * mm.y + 0.729f * p.y;
        r.z = 0.81f * mm.z + 0.729f * p.z;
        r.w = 0.81f * mm.w + 0.729f * p.w;
        *(float4*)&g_R[base] = r;
    }
}

// ============================================================================
// Kernel B: final = M + 0.9P + P @ R  ; write final^T.  Dense single matmul.
// grid(256), block(256). 16 rows/block, 2x4 tile/thread.
// ============================================================================
__global__ __launch_bounds__(256) void prepB_kernel(const float* __restrict__ relmask)
{
    int bid = blockIdx.x;
    int t = threadIdx.x;
    int b  = bid >> 3;
    int n0 = (bid & 7) * 16;
    const float* Pb = g_P + (size_t)b * NF * NF;
    const float* Rb = g_R + (size_t)b * NF * NF;
    const float* Mb = relmask + (size_t)b * NF * NF;

    __shared__ float csh[16][NF];        // P rows n0..n0+15 (left operand)
    __shared__ float msm[16][NF];        // M rows n0..n0+15 (for the + M term)
    __shared__ float msh[2][32][NF];     // double-buffered R k-tile

    {
        const float4* srcP = (const float4*)(Pb + (size_t)n0 * NF);
        const float4* srcM = (const float4*)(Mb + (size_t)n0 * NF);
        float4* dstP = (float4*)&csh[0][0];
        float4* dstM = (float4*)&msm[0][0];
        cp_async16(dstP + t,       srcP + t);
        cp_async16(dstP + t + 256, srcP + t + 256);
        cp_async16(dstM + t,       srcM + t);
        cp_async16(dstM + t + 256, srcM + t + 256);
    }
    {
        const float4* src = (const float4*)Rb;
        float4* dst = (float4*)&msh[0][0][0];
        #pragma unroll
        for (int i = 0; i < 4; i++)
            cp_async16(dst + t + 256 * i, src + t + 256 * i);
    }
    asm volatile("cp.async.commit_group;");
    asm volatile("cp.async.wait_group 0;");
    __syncthreads();

    int tn = (t >> 5) * 2;
    int tm = (t & 31) * 4;

    float acc0[4] = {}, acc1[4] = {};
    for (int kt = 0; kt < 4; kt++) {
        if (kt < 3) {
            const float4* src = (const float4*)(Rb + (size_t)(kt + 1) * 32 * NF);
            float4* dst = (float4*)&msh[(kt + 1) & 1][0][0];
            #pragma unroll
            for (int i = 0; i < 4; i++)
                cp_async16(dst + t + 256 * i, src + t + 256 * i);
            asm volatile("cp.async.commit_group;");
            asm volatile("cp.async.wait_group 1;");
        } else {
            asm volatile("cp.async.wait_group 0;");
        }
        __syncthreads();

        const float (*mb)[NF] = msh[kt & 1];
        #pragma unroll
        for (int kk4 = 0; kk4 < 8; kk4++) {
            float cva[4], cvb[4];
            *(float4*)cva = *(const float4*)&csh[tn + 0][kt * 32 + kk4 * 4];
            *(float4*)cvb = *(const float4*)&csh[tn + 1][kt * 32 + kk4 * 4];
            #pragma unroll
            for (int j = 0; j < 4; j++) {
                float4 mv = *(const float4*)&mb[kk4 * 4 + j][tm];
                acc0[0] += cva[j] * mv.x; acc0[1] += cva[j] * mv.y;
                acc0[2] += cva[j] * mv.z; acc0[3] += cva[j] * mv.w;
                acc1[0] += cvb[j] * mv.x; acc1[1] += cvb[j] * mv.y;
                acc1[2] += cvb[j] * mv.z; acc1[3] += cvb[j] * mv.w;
            }
        }
        __syncthreads();
    }

    // f = M + 0.9*P + acc ; stage into csh for transpose
    float4 f0, f1;
    {
        float4 mm = *(const float4*)&msm[tn + 0][tm];
        float4 pp = *(const float4*)&csh[tn + 0][tm];
        f0.x = mm.x + 0.9f * pp.x + acc0[0];
        f0.y = mm.y + 0.9f * pp.y + acc0[1];
        f0.z = mm.z + 0.9f * pp.z + acc0[2];
        f0.w = mm.w + 0.9f * pp.w + acc0[3];
        mm = *(const float4*)&msm[tn + 1][tm];
        pp = *(const float4*)&csh[tn + 1][tm];
        f1.x = mm.x + 0.9f * pp.x + acc1[0];
        f1.y = mm.y + 0.9f * pp.y + acc1[1];
        f1.z = mm.z + 0.9f * pp.z + acc1[2];
        f1.w = mm.w + 0.9f * pp.w + acc1[3];
    }
    __syncthreads();
    *(float4*)&csh[tn + 0][tm] = f0;
    *(float4*)&csh[tn + 1][tm] = f1;
    __syncthreads();
    {
        int m = t >> 1, half = (t & 1) * 8;
        float v[8];
        #pragma unroll
        for (int i = 0; i < 8; i++) v[i] = csh[half + i][m];
        float* dstT = g_finalT + ((size_t)b * NF + m) * NF + n0 + half;
        *(float4*)&dstT[0] = make_float4(v[0], v[1], v[2], v[3]);
        *(float4*)&dstT[4] = make_float4(v[4], v[5], v[6], v[7]);
    }
}

// ============================================================================
// Kernel 2: main stream.  Block = (b, m).  Quarter-warp dot products with
// explicit 2-stage register double-buffering of the feat_edge loads.
// grid(B*NF), block(256) = 8 warps x 16 rows each (4 rows per warp-iter).
// ============================================================================
__global__ __launch_bounds__(256) void main_kernel(const float* __restrict__ fe)
{
    int bid = blockIdx.x;
    int b = bid >> 7;
    int m = bid & 127;
    __shared__ float qsh[DE];
    __shared__ float ash[NF * G];
    __shared__ float msk[NF];
    __shared__ float part[8][2];

    int t = threadIdx.x;
    qsh[t] = g_query[b * DE + t];
    ash[t] = g_attin[b * NF * G + t];
    if (t < NF) msk[t] = g_finalT[((size_t)b * NF + m) * NF + t];
    __syncthreads();

    int w = t >> 5, lane = t & 31;
    int qq = lane >> 3, sub = lane & 7;
    const float4* qp = (const float4*)qsh;
    const float* febase = fe + (((size_t)b * NF) * NF + m) * DE;

    float4 cur[8];
    {
        const float4* row = (const float4*)(febase + (size_t)(w + 8 * qq) * NF * DE);
        #pragma unroll
        for (int c = 0; c < 8; c++) cur[c] = __ldcs(&row[sub + 8 * c]);
    }

    float p0 = 0.f, p1 = 0.f;
    #pragma unroll
    for (int j = 0; j < 4; j++) {
        float4 nxt[8];
        if (j < 3) {
            int n2 = w + 8 * (4 * (j + 1) + qq);
            const float4* row = (const float4*)(febase + (size_t)n2 * NF * DE);
            #pragma unroll
            for (int c = 0; c < 8; c++) nxt[c] = __ldcs(&row[sub + 8 * c]);
        }

        float sA = 0.f, sB = 0.f;
        #pragma unroll
        for (int c = 0; c < 8; c += 2) {
            float4 q0 = qp[sub + 8 * c];
            float4 q1 = qp[sub + 8 * (c + 1)];
            sA += cur[c].x * q0.x + cur[c].y * q0.y
                + cur[c].z * q0.z + cur[c].w * q0.w;
            sB += cur[c+1].x * q1.x + cur[c+1].y * q1.y
                + cur[c+1].z * q1.z + cur[c+1].w * q1.w;
        }
        float s = sA + sB;
        s += __shfl_xor_sync(~0u, s, 1);
        s += __shfl_xor_sync(~0u, s, 2);
        s += __shfl_xor_sync(~0u, s, 4);
        int n = w + 8 * (4 * j + qq);
        float wv = msk[n] / (1.f + __expf(-s));
        p0 += ash[n * 2]     * wv;
        p1 += ash[n * 2 + 1] * wv;

        #pragma unroll
        for (int c = 0; c < 8; c++) cur[c] = nxt[c];
    }
    p0 += __shfl_xor_sync(~0u, p0, 8);
    p0 += __shfl_xor_sync(~0u, p0, 16);
    p1 += __shfl_xor_sync(~0u, p1, 8);
    p1 += __shfl_xor_sync(~0u, p1, 16);

    if (lane == 0) { part[w][0] = p0; part[w][1] = p1; }
    __syncthreads();
    if (t < 2) {
        float s = 0.f;
        #pragma unroll
        for (int i = 0; i < 8; i++) s += part[i][t];
        g_attout[((size_t)b * NF + m) * G + t] = s;
    }
}

// ============================================================================
// Kernel 3: normalize + blend + write all four outputs.  grid(B), block(256)
// ============================================================================
__global__ __launch_bounds__(256) void finalize_kernel(
    const float* __restrict__ att_stack, const float* __restrict__ stack_ptr,
    float* __restrict__ out)
{
    int b = blockIdx.x;
    int t = threadIdx.x;
    __shared__ float att[NF * G];
    __shared__ float norm[G];
    __shared__ float sps[SL];

    att[t] = g_attout[b * NF * G + t];
    if (t < SL) sps[t] = stack_ptr[b * SL + t];
    __syncthreads();

    if (t < 64) {
        int g = t >> 5, lane = t & 31;
        float mx = -1e30f;
        for (int i = lane; i < NF; i += 32) mx = fmaxf(mx, att[i * G + g]);
        #pragma unroll
        for (int o = 16; o; o >>= 1) mx = fmaxf(mx, __shfl_xor_sync(~0u, mx, o));
        if (lane == 0) norm[g] = (mx <= 1.f) ? 1.f : mx;
    }
    __syncthreads();

    const float* asb = att_stack + (size_t)b * NF * G * SL;
    float* ob = out + (size_t)b * NF * G * SL;
    for (int idx = t; idx < NF * G * SL; idx += 256) {
        int s = idx & 7;
        int g = (idx >> 3) & 1;
        int n = idx >> 4;
        float a  = att[n * G + g] / norm[g];
        float sp = sps[s];
        ob[idx] = a * sp + asb[idx] * (1.f - sp);
    }
    if (t < SL) out[(size_t)B * NF * G * SL + b * SL + t] = sps[t];
    float* z = out + (size_t)B * NF * G * SL + (size_t)B * SL;
    for (int i = t; i < DH; i += 256) {
        z[(size_t)b * DH + i] = 0.f;
        z[(size_t)B * DH + (size_t)b * DH + i] = 0.f;
    }
}

// ============================================================================
extern "C" void kernel_launch(void* const* d_in, const int* in_sizes, int n_in,
                              void* d_out, int out_size)
{
    const float* feat_edge = (const float*)d_in[2];
    const float* c_i       = (const float*)d_in[3];
    const float* relmask   = (const float*)d_in[4];
    const float* att_stack = (const float*)d_in[5];
    const float* stack_ptr = (const float*)d_in[6];
    const float* map_c_w   = (const float*)d_in[8];
    const float* map_c_b   = (const float*)d_in[9];
    float* out = (float*)d_out;

    prepA_kernel<<<256 + B, 256>>>(relmask, c_i, map_c_w, map_c_b,
                                   att_stack, stack_ptr);
    prepB_kernel<<<256, 256>>>(relmask);
    main_kernel<<<B * NF, 256>>>(feat_edge);
    finalize_kernel<<<B, 256>>>(att_stack, stack_ptr, out);
}

// round 6
// speedup vs baseline: 1.3451x; 1.0781x over previous
#include <cuda_runtime.h>
#include <math.h>

#define B   32
#define NF  128
#define DE  256
#define DH  512
#define G   2
#define SL  8

// ---- device scratch (no allocations allowed) ----
__device__ float g_query[B * DE];
__device__ float g_attin[B * NF * G];
__device__ float g_P[B * NF * NF];       // M @ M
__device__ float g_R[B * NF * NF];       // 0.81*M + 0.729*P
__device__ float g_finalT[B * NF * NF];  // final mask, transposed [b][m][n]
__device__ float g_sig[B * NF * NF];     // sigmoid(fe . q), layout [b][m][n]

__device__ __forceinline__ void cp_async16(void* smem_dst, const void* gmem_src) {
    unsigned sa = (unsigned)__cvta_generic_to_shared(smem_dst);
    asm volatile("cp.async.ca.shared.global [%0], [%1], 16;" :: "r"(sa), "l"(gmem_src));
}

// ============================================================================
// Kernel 1: prepA (P = M@M sparse-sparse, R = 0.81M + 0.729P) for bid < 256,
// query = c_i@W^T + b and att_in einsum for bid >= 256.  grid(288), 256 thr.
// ============================================================================
__global__ __launch_bounds__(256) void k1_prepA_query(
    const float* __restrict__ relmask,
    const float* __restrict__ c_i, const float* __restrict__ W,
    const float* __restrict__ bias,
    const float* __restrict__ att_stack, const float* __restrict__ stack_ptr)
{
    int bid = blockIdx.x;
    int t = threadIdx.x;

    if (bid >= 256) {
        int b = bid - 256;
        __shared__ float qc[DH];
        qc[t]       = c_i[b * DH + t];
        qc[t + 256] = c_i[b * DH + t + 256];
        __syncthreads();

        int w = t >> 5, lane = t & 31;
        for (int d = w; d < DE; d += 8) {
            const float* Wr = W + (size_t)d * DH;
            float s = 0.f;
            #pragma unroll
            for (int i = 0; i < DH / 32; i++)
                s += Wr[lane + 32 * i] * qc[lane + 32 * i];
            #pragma unroll
            for (int o = 16; o; o >>= 1) s += __shfl_xor_sync(~0u, s, o);
            if (lane == 0) g_query[b * DE + d] = s + bias[d];
        }
        {
            int n = t >> 1, g = t & 1;
            const float* as = att_stack + (((size_t)b * NF + n) * G + g) * SL;
            const float* sp = stack_ptr + b * SL;
            float s = 0.f;
            #pragma unroll
            for (int ss = 0; ss < SL; ss++) s += as[ss] * sp[ss];
            g_attin[(b * NF + n) * G + g] = s;
        }
        return;
    }

    int b  = bid >> 3;
    int n0 = (bid & 7) * 16;
    const float* Mb = relmask + (size_t)b * NF * NF;

    __shared__ float csh[16][NF];
    __shared__ float msh[2][32][NF];

    {
        const float4* src = (const float4*)(Mb + (size_t)n0 * NF);
        float4* dst = (float4*)&csh[0][0];
        cp_async16(dst + t,       src + t);
        cp_async16(dst + t + 256, src + t + 256);
    }
    {
        const float4* src = (const float4*)Mb;
        float4* dst = (float4*)&msh[0][0][0];
        #pragma unroll
        for (int i = 0; i < 4; i++)
            cp_async16(dst + t + 256 * i, src + t + 256 * i);
    }
    asm volatile("cp.async.commit_group;");
    asm volatile("cp.async.wait_group 0;");
    __syncthreads();

    int tn = (t >> 5) * 2;
    int tm = (t & 31) * 4;

    float acc0[4] = {}, acc1[4] = {};
    for (int kt = 0; kt < 4; kt++) {
        if (kt < 3) {
            const float4* src = (const float4*)(Mb + (size_t)(kt + 1) * 32 * NF);
            float4* dst = (float4*)&msh[(kt + 1) & 1][0][0];
            #pragma unroll
            for (int i = 0; i < 4; i++)
                cp_async16(dst + t + 256 * i, src + t + 256 * i);
            asm volatile("cp.async.commit_group;");
            asm volatile("cp.async.wait_group 1;");
        } else {
            asm volatile("cp.async.wait_group 0;");
        }
        __syncthreads();

        const float (*mb)[NF] = msh[kt & 1];
        #pragma unroll
        for (int kk4 = 0; kk4 < 8; kk4++) {
            float cva[4], cvb[4];
            *(float4*)cva = *(const float4*)&csh[tn + 0][kt * 32 + kk4 * 4];
            *(float4*)cvb = *(const float4*)&csh[tn + 1][kt * 32 + kk4 * 4];
            #pragma unroll
            for (int j = 0; j < 4; j++) {
                float ca = cva[j], cb2 = cvb[j];
                if (ca != 0.f || cb2 != 0.f) {   // warp-uniform skip (~90%)
                    float4 mv = *(const float4*)&mb[kk4 * 4 + j][tm];
                    acc0[0] += ca * mv.x;  acc0[1] += ca * mv.y;
                    acc0[2] += ca * mv.z;  acc0[3] += ca * mv.w;
                    acc1[0] += cb2 * mv.x; acc1[1] += cb2 * mv.y;
                    acc1[2] += cb2 * mv.z; acc1[3] += cb2 * mv.w;
                }
            }
        }
        __syncthreads();
    }

    #pragma unroll
    for (int i = 0; i < 2; i++) {
        const float* acc = (i == 0) ? acc0 : acc1;
        size_t base = ((size_t)b * NF + n0 + tn + i) * NF + tm;
        float4 p = make_float4(acc[0], acc[1], acc[2], acc[3]);
        *(float4*)&g_P[base] = p;
        float4 mm = *(const float4*)&csh[tn + i][tm];
        float4 r;
        r.x = 0.81f * mm.x + 0.729f * p.x;
        r.y = 0.81f * mm.y + 0.729f * p.y;
        r.z = 0.81f * mm.z + 0.729f * p.z;
        r.w = 0.81f * mm.w + 0.729f * p.w;
        *(float4*)&g_R[base] = r;
    }
}

// ============================================================================
// Kernel 2: combined launch.
//   bid < 256  : prepB — final = M + 0.9P + P@R, write final^T.
//   bid >= 256 : sigma stream — sig[b,m,n] = sigmoid(fe[b,n,m,:].q[b,:]).
// Mask blocks first so they finish inside wave 1 while sigma saturates DRAM.
// grid(256 + B*NF), block(256).  Shared memory overlaid (union, 48KB max).
// ============================================================================
__global__ __launch_bounds__(256) void k2_prepB_sigma(
    const float* __restrict__ relmask, const float* __restrict__ fe)
{
    __shared__ __align__(16) char shraw[49152];
    int bid = blockIdx.x;
    int t = threadIdx.x;

    if (bid < 256) {
        // ---------------- prepB ----------------
        int b  = bid >> 3;
        int n0 = (bid & 7) * 16;
        const float* Pb = g_P + (size_t)b * NF * NF;
        const float* Rb = g_R + (size_t)b * NF * NF;
        const float* Mb = relmask + (size_t)b * NF * NF;

        float (*csh)[NF] = (float(*)[NF])shraw;                 // 8KB: P rows
        float (*msm)[NF] = (float(*)[NF])(shraw + 8192);        // 8KB: M rows
        float (*msh)[32][NF] = (float(*)[32][NF])(shraw + 16384); // 32KB

        {
            const float4* srcP = (const float4*)(Pb + (size_t)n0 * NF);
            const float4* srcM = (const float4*)(Mb + (size_t)n0 * NF);
            float4* dstP = (float4*)&csh[0][0];
            float4* dstM = (float4*)&msm[0][0];
            cp_async16(dstP + t,       srcP + t);
            cp_async16(dstP + t + 256, srcP + t + 256);
            cp_async16(dstM + t,       srcM + t);
            cp_async16(dstM + t + 256, srcM + t + 256);
        }
        {
            const float4* src = (const float4*)Rb;
            float4* dst = (float4*)&msh[0][0][0];
            #pragma unroll
            for (int i = 0; i < 4; i++)
                cp_async16(dst + t + 256 * i, src + t + 256 * i);
        }
        asm volatile("cp.async.commit_group;");
        asm volatile("cp.async.wait_group 0;");
        __syncthreads();

        int tn = (t >> 5) * 2;
        int tm = (t & 31) * 4;

        float acc0[4] = {}, acc1[4] = {};
        for (int kt = 0; kt < 4; kt++) {
            if (kt < 3) {
                const float4* src = (const float4*)(Rb + (size_t)(kt + 1) * 32 * NF);
                float4* dst = (float4*)&msh[(kt + 1) & 1][0][0];
                #pragma unroll
                for (int i = 0; i < 4; i++)
                    cp_async16(dst + t + 256 * i, src + t + 256 * i);
                asm volatile("cp.async.commit_group;");
                asm volatile("cp.async.wait_group 1;");
            } else {
                asm volatile("cp.async.wait_group 0;");
            }
            __syncthreads();

            const float (*mb)[NF] = msh[kt & 1];
            #pragma unroll
            for (int kk4 = 0; kk4 < 8; kk4++) {
                float cva[4], cvb[4];
                *(float4*)cva = *(const float4*)&csh[tn + 0][kt * 32 + kk4 * 4];
                *(float4*)cvb = *(const float4*)&csh[tn + 1][kt * 32 + kk4 * 4];
                #pragma unroll
                for (int j = 0; j < 4; j++) {
                    float4 mv = *(const float4*)&mb[kk4 * 4 + j][tm];
                    acc0[0] += cva[j] * mv.x; acc0[1] += cva[j] * mv.y;
                    acc0[2] += cva[j] * mv.z; acc0[3] += cva[j] * mv.w;
                    acc1[0] += cvb[j] * mv.x; acc1[1] += cvb[j] * mv.y;
                    acc1[2] += cvb[j] * mv.z; acc1[3] += cvb[j] * mv.w;
                }
            }
            __syncthreads();
        }

        float4 f0, f1;
        {
            float4 mm = *(const float4*)&msm[tn + 0][tm];
            float4 pp = *(const float4*)&csh[tn + 0][tm];
            f0.x = mm.x + 0.9f * pp.x + acc0[0];
            f0.y = mm.y + 0.9f * pp.y + acc0[1];
            f0.z = mm.z + 0.9f * pp.z + acc0[2];
            f0.w = mm.w + 0.9f * pp.w + acc0[3];
            mm = *(const float4*)&msm[tn + 1][tm];
            pp = *(const float4*)&csh[tn + 1][tm];
            f1.x = mm.x + 0.9f * pp.x + acc1[0];
            f1.y = mm.y + 0.9f * pp.y + acc1[1];
            f1.z = mm.z + 0.9f * pp.z + acc1[2];
            f1.w = mm.w + 0.9f * pp.w + acc1[3];
        }
        __syncthreads();
        *(float4*)&csh[tn + 0][tm] = f0;
        *(float4*)&csh[tn + 1][tm] = f1;
        __syncthreads();
        {
            int m = t >> 1, half = (t & 1) * 8;
            float v[8];
            #pragma unroll
            for (int i = 0; i < 8; i++) v[i] = csh[half + i][m];
            float* dstT = g_finalT + ((size_t)b * NF + m) * NF + n0 + half;
            *(float4*)&dstT[0] = make_float4(v[0], v[1], v[2], v[3]);
            *(float4*)&dstT[4] = make_float4(v[4], v[5], v[6], v[7]);
        }
        return;
    }

    // ---------------- sigma stream ----------------
    int id = bid - 256;
    int b = id >> 7;
    int m = id & 127;
    float* qsh = (float*)shraw;          // 1KB
    float* sig = qsh + DE;               // 0.5KB

    qsh[t] = g_query[b * DE + t];
    __syncthreads();

    int w = t >> 5, lane = t & 31;
    int qq = lane >> 3, sub = lane & 7;
    const float4* qp = (const float4*)qsh;
    const float* febase = fe + (((size_t)b * NF) * NF + m) * DE;

    float4 cur[8];
    {
        const float4* row = (const float4*)(febase + (size_t)(w + 8 * qq) * NF * DE);
        #pragma unroll
        for (int c = 0; c < 8; c++) cur[c] = __ldcs(&row[sub + 8 * c]);
    }

    #pragma unroll
    for (int j = 0; j < 4; j++) {
        float4 nxt[8];
        if (j < 3) {
            int n2 = w + 8 * (4 * (j + 1) + qq);
            const float4* row = (const float4*)(febase + (size_t)n2 * NF * DE);
            #pragma unroll
            for (int c = 0; c < 8; c++) nxt[c] = __ldcs(&row[sub + 8 * c]);
        }

        float sA = 0.f, sB = 0.f;
        #pragma unroll
        for (int c = 0; c < 8; c += 2) {
            float4 q0 = qp[sub + 8 * c];
            float4 q1 = qp[sub + 8 * (c + 1)];
            sA += cur[c].x * q0.x + cur[c].y * q0.y
                + cur[c].z * q0.z + cur[c].w * q0.w;
            sB += cur[c+1].x * q1.x + cur[c+1].y * q1.y
                + cur[c+1].z * q1.z + cur[c+1].w * q1.w;
        }
        float s = sA + sB;
        s += __shfl_xor_sync(~0u, s, 1);
        s += __shfl_xor_sync(~0u, s, 2);
        s += __shfl_xor_sync(~0u, s, 4);
        int n = w + 8 * (4 * j + qq);
        if (sub == 0) sig[n] = 1.f / (1.f + __expf(-s));

        #pragma unroll
        for (int c = 0; c < 8; c++) cur[c] = nxt[c];
    }
    __syncthreads();
    if (t < NF)
        g_sig[((size_t)b * NF + m) * NF + t] = sig[t];
}

// ============================================================================
// Kernel 3: masked contraction + norm + blend + all outputs.
// grid(B), block(512).  Each warp handles 8 m-rows; per row one float4/lane.
// ============================================================================
__global__ __launch_bounds__(512) void k3_final(
    const float* __restrict__ att_stack, const float* __restrict__ stack_ptr,
    float* __restrict__ out)
{
    int b = blockIdx.x;
    int t = threadIdx.x;
    __shared__ float ash[NF * G];
    __shared__ float att[NF * G];
    __shared__ float norm[G];
    __shared__ float sps[SL];

    if (t < NF * G) ash[t] = g_attin[b * NF * G + t];
    if (t < SL) sps[t] = stack_ptr[b * SL + t];
    __syncthreads();

    int w = t >> 5, lane = t & 31;
    const float4* ap = (const float4*)ash;
    float4 a01 = ap[2 * lane], a23 = ap[2 * lane + 1];

    #pragma unroll
    for (int r = 0; r < 8; r++) {
        int m = w + 16 * r;
        const float4* fr = (const float4*)(g_finalT + ((size_t)b * NF + m) * NF);
        const float4* sr = (const float4*)(g_sig    + ((size_t)b * NF + m) * NF);
        float4 f = fr[lane];
        float4 s = sr[lane];
        float w0 = f.x * s.x, w1 = f.y * s.y, w2 = f.z * s.z, w3 = f.w * s.w;
        float p0 = w0 * a01.x + w1 * a01.z + w2 * a23.x + w3 * a23.z;
        float p1 = w0 * a01.y + w1 * a01.w + w2 * a23.y + w3 * a23.w;
        #pragma unroll
        for (int o = 16; o; o >>= 1) {
            p0 += __shfl_xor_sync(~0u, p0, o);
            p1 += __shfl_xor_sync(~0u, p1, o);
        }
        if (lane == 0) { att[m * 2] = p0; att[m * 2 + 1] = p1; }
    }
    __syncthreads();

    if (t < 64) {
        int g = t >> 5, ln = t & 31;
        float mx = -1e30f;
        for (int i = ln; i < NF; i += 32) mx = fmaxf(mx, att[i * G + g]);
        #pragma unroll
        for (int o = 16; o; o >>= 1) mx = fmaxf(mx, __shfl_xor_sync(~0u, mx, o));
        if (ln == 0) norm[g] = (mx <= 1.f) ? 1.f : mx;
    }
    __syncthreads();

    const float* asb = att_stack + (size_t)b * NF * G * SL;
    float* ob = out + (size_t)b * NF * G * SL;
    for (int idx = t; idx < NF * G * SL; idx += 512) {
        int s = idx & 7;
        int g = (idx >> 3) & 1;
        int n = idx >> 4;
        float a  = att[n * G + g] / norm[g];
        float sp = sps[s];
        ob[idx] = a * sp + asb[idx] * (1.f - sp);
    }
    if (t < SL) out[(size_t)B * NF * G * SL + b * SL + t] = sps[t];
    float* z = out + (size_t)B * NF * G * SL + (size_t)B * SL;
    for (int i = t; i < DH; i += 512) {
        z[(size_t)b * DH + i] = 0.f;
        z[(size_t)B * DH + (size_t)b * DH + i] = 0.f;
    }
}

// ============================================================================
extern "C" void kernel_launch(void* const* d_in, const int* in_sizes, int n_in,
                              void* d_out, int out_size)
{
    const float* feat_edge = (const float*)d_in[2];
    const float* c_i       = (const float*)d_in[3];
    const float* relmask   = (const float*)d_in[4];
    const float* att_stack = (const float*)d_in[5];
    const float* stack_ptr = (const float*)d_in[6];
    const float* map_c_w   = (const float*)d_in[8];
    const float* map_c_b   = (const float*)d_in[9];
    float* out = (float*)d_out;

    k1_prepA_query<<<256 + B, 256>>>(relmask, c_i, map_c_w, map_c_b,
                                     att_stack, stack_ptr);
    k2_prepB_sigma<<<256 + B * NF, 256>>>(relmask, feat_edge);
    k3_final<<<B, 512>>>(att_stack, stack_ptr, out);
}